// round 13
// baseline (speedup 1.0000x reference)
#include <cuda_runtime.h>

// Bilinear 2x upsample NHWC f32: (8,256,256,32) -> (8,512,512,32).
// Two kernels:
//  1) Interior quad kernel: tight grid (8,256,8), all blocks full, no
//     early-return, regs ~32 (high occupancy). Each thread: one 2x2 output
//     quad (rows/cols 0..510) from a 2x2 input patch per float4 channel
//     group. j=0/k=0 clamps duplicate col/row 0 with identical values.
//  2) Edge kernel: output col 511 + row 511 (~1MB) via the general verified
//     closed-form scale-0.5 math. Disjoint coverage, both graph-capturable.

#define IH 256
#define IW 256
#define OH 512
#define OW 512
#define C4 8          // 32 channels / 4 floats

__global__ __launch_bounds__(256) void bilinear2x_interior_kernel(
    const float4* __restrict__ in, float4* __restrict__ out)
{
    // threadIdx.x: 8 channel-groups (c4, fastest) x 32 x-quads per block
    const int c4 = threadIdx.x & (C4 - 1);
    const int j  = blockIdx.x * 32 + (threadIdx.x >> 3);   // 0..255
    const int k  = blockIdx.y;                              // 0..255
    const int n  = blockIdx.z;

    const int ya = max(k - 1, 0);
    const int yb = k;
    const int xa = max(j - 1, 0);
    const int xb = j;

    const float4* __restrict__ ibase = in + (long long)n * (IH * IW * C4);
    const float4 vaa = __ldg(ibase + (ya * IW + xa) * C4 + c4);
    const float4 vab = __ldg(ibase + (ya * IW + xb) * C4 + c4);
    const float4 vba = __ldg(ibase + (yb * IW + xa) * C4 + c4);
    const float4 vbb = __ldg(ibase + (yb * IW + xb) * C4 + c4);

    // Separable x-interps: w_right = 0.25 (left out col), 0.75 (right)
    float4 tL, tR, bL, bR;
    tL.x = 0.75f * vaa.x + 0.25f * vab.x;  tR.x = 0.25f * vaa.x + 0.75f * vab.x;
    tL.y = 0.75f * vaa.y + 0.25f * vab.y;  tR.y = 0.25f * vaa.y + 0.75f * vab.y;
    tL.z = 0.75f * vaa.z + 0.25f * vab.z;  tR.z = 0.25f * vaa.z + 0.75f * vab.z;
    tL.w = 0.75f * vaa.w + 0.25f * vab.w;  tR.w = 0.25f * vaa.w + 0.75f * vab.w;
    bL.x = 0.75f * vba.x + 0.25f * vbb.x;  bR.x = 0.25f * vba.x + 0.75f * vbb.x;
    bL.y = 0.75f * vba.y + 0.25f * vbb.y;  bR.y = 0.25f * vba.y + 0.75f * vbb.y;
    bL.z = 0.75f * vba.z + 0.25f * vbb.z;  bR.z = 0.25f * vba.z + 0.75f * vbb.z;
    bL.w = 0.75f * vba.w + 0.25f * vbb.w;  bR.w = 0.25f * vba.w + 0.75f * vbb.w;

    const int r0 = max(2 * k - 1, 0);
    const int r1 = 2 * k;
    const int c0 = max(2 * j - 1, 0);
    const int c1 = 2 * j;

    float4* __restrict__ obase = out + (long long)n * (OH * OW * C4);

    float4 o;
    o.x = 0.75f * tL.x + 0.25f * bL.x;
    o.y = 0.75f * tL.y + 0.25f * bL.y;
    o.z = 0.75f * tL.z + 0.25f * bL.z;
    o.w = 0.75f * tL.w + 0.25f * bL.w;
    obase[(r0 * OW + c0) * C4 + c4] = o;

    o.x = 0.75f * tR.x + 0.25f * bR.x;
    o.y = 0.75f * tR.y + 0.25f * bR.y;
    o.z = 0.75f * tR.z + 0.25f * bR.z;
    o.w = 0.75f * tR.w + 0.25f * bR.w;
    obase[(r0 * OW + c1) * C4 + c4] = o;

    o.x = 0.25f * tL.x + 0.75f * bL.x;
    o.y = 0.25f * tL.y + 0.75f * bL.y;
    o.z = 0.25f * tL.z + 0.75f * bL.z;
    o.w = 0.25f * tL.w + 0.75f * bL.w;
    obase[(r1 * OW + c0) * C4 + c4] = o;

    o.x = 0.25f * tR.x + 0.75f * bR.x;
    o.y = 0.25f * tR.y + 0.75f * bR.y;
    o.z = 0.25f * tR.z + 0.75f * bR.z;
    o.w = 0.25f * tR.w + 0.75f * bR.w;
    obase[(r1 * OW + c1) * C4 + c4] = o;
}

// Edge kernel: writes output col 511 (rows 0..511) and row 511 (cols 0..510).
// General closed-form scale-0.5 bilinear (verified Round-1 math).
// Edge pixels per batch: 512 (col 511) + 511 (row 511 w/o corner) = 1023.
// Threads: n(8) x pixel(1023) x c4(8) = 65,472.
__global__ __launch_bounds__(256) void bilinear2x_edge_kernel(
    const float4* __restrict__ in, float4* __restrict__ out)
{
    const int tid = blockIdx.x * 256 + threadIdx.x;
    const int total = 8 * 1023 * C4;
    if (tid >= total) return;

    const int c4 = tid & (C4 - 1);
    const int p  = (tid >> 3) % 1023;         // pixel index 0..1022
    const int n  = (tid >> 3) / 1023;

    int oy, ox;
    if (p < 512) { ox = OW - 1; oy = p; }     // col 511, rows 0..511
    else         { oy = OH - 1; ox = p - 512; } // row 511, cols 0..510

    const float gy = fmaxf((float)oy * 0.5f - 0.25f, 0.0f);
    const float gx = fmaxf((float)ox * 0.5f - 0.25f, 0.0f);
    const int y0 = (int)gy;
    const int x0 = (int)gx;
    const float h0 = gy - (float)y0;
    const float w0 = gx - (float)x0;
    const int y1 = y0 + (y0 < IH - 1);
    const int x1 = x0 + (x0 < IW - 1);
    const float h1 = 1.0f - h0;
    const float w1 = 1.0f - w0;

    const float4* __restrict__ ibase = in + (long long)n * (IH * IW * C4);
    const float4 v00 = __ldg(ibase + (y0 * IW + x0) * C4 + c4);
    const float4 v01 = __ldg(ibase + (y0 * IW + x1) * C4 + c4);
    const float4 v10 = __ldg(ibase + (y1 * IW + x0) * C4 + c4);
    const float4 v11 = __ldg(ibase + (y1 * IW + x1) * C4 + c4);

    float4 r;
    r.x = h1 * (w1 * v00.x + w0 * v01.x) + h0 * (w1 * v10.x + w0 * v11.x);
    r.y = h1 * (w1 * v00.y + w0 * v01.y) + h0 * (w1 * v10.y + w0 * v11.y);
    r.z = h1 * (w1 * v00.z + w0 * v01.z) + h0 * (w1 * v10.z + w0 * v11.z);
    r.w = h1 * (w1 * v00.w + w0 * v01.w) + h0 * (w1 * v10.w + w0 * v11.w);

    out[(long long)n * (OH * OW * C4) + ((long long)oy * OW + ox) * C4 + c4] = r;
}

extern "C" void kernel_launch(void* const* d_in, const int* in_sizes, int n_in,
                              void* d_out, int out_size)
{
    const float4* in  = (const float4*)d_in[0];
    float4*       out = (float4*)d_out;

    dim3 block(256, 1, 1);
    dim3 grid(IW / 32, IH, 8);               // (8, 256, 8) — all blocks full
    bilinear2x_interior_kernel<<<grid, block>>>(in, out);

    const int edge_total = 8 * 1023 * C4;    // 65,472
    bilinear2x_edge_kernel<<<(edge_total + 255) / 256, 256>>>(in, out);
}